// round 1
// baseline (speedup 1.0000x reference)
#include <cuda_runtime.h>
#include <math.h>

// ---------------- problem constants ----------------
#define BB 4
#define TT 16
#define SSQ 256
#define DD 1024
#define HH 16
#define HDIM 64
#define HIDDEN 2752
#define TOKENS (BB*TT*SSQ)      /* 16384 */
#define SIXD (6*DD)             /* 6144  */

// ---------------- scratch (static device globals; no runtime alloc) -------
__device__ float g_mod[BB*SIXD];
__device__ float g_h[(size_t)TOKENS*DD];
__device__ float g_qkv[(size_t)TOKENS*3*DD];
__device__ float g_attn[(size_t)TOKENS*DD];
__device__ float g_proj[(size_t)TOKENS*DD];
__device__ float g_ff1[(size_t)TOKENS*HIDDEN];
__device__ float g_ff2[(size_t)TOKENS*HIDDEN];
__device__ float g_ffo[(size_t)TOKENS*DD];

// ---------------- mod = silu(time_emb) @ mod_w + mod_b --------------------
__global__ void mod_kernel(const float* __restrict__ te,
                           const float* __restrict__ mod_w,
                           const float* __restrict__ mod_b,
                           float* __restrict__ mod) {
    __shared__ float s[DD];
    int b = blockIdx.y;
    int j = blockIdx.x * 256 + threadIdx.x;
    for (int d = threadIdx.x; d < DD; d += 256) {
        float v = te[b*DD + d];
        s[d] = v / (1.f + __expf(-v));
    }
    __syncthreads();
    float acc = mod_b[j];
    #pragma unroll 4
    for (int d = 0; d < DD; d++)
        acc = fmaf(s[d], mod_w[(size_t)d*SIXD + j], acc);
    mod[b*SIXD + j] = acc;
}

// ---------- h = rmsnorm(x, w) * (1 + scale) + shift  (one CTA per token) --
__global__ void norm_mod_kernel(const float* __restrict__ x,
                                const float* __restrict__ w,
                                const float* __restrict__ mod,
                                int shift_off, int scale_off,
                                float* __restrict__ out) {
    __shared__ float red[8];
    int t = blockIdx.x;
    int b = t >> 12;              // / (TT*SSQ) = /4096
    int tid = threadIdx.x;
    const float4* x4 = (const float4*)(x + (size_t)t*DD);
    float4 v = x4[tid];
    float ss = v.x*v.x + v.y*v.y + v.z*v.z + v.w*v.w;
    #pragma unroll
    for (int o = 16; o > 0; o >>= 1) ss += __shfl_xor_sync(0xffffffffu, ss, o);
    if ((tid & 31) == 0) red[tid >> 5] = ss;
    __syncthreads();
    float tot = red[0]+red[1]+red[2]+red[3]+red[4]+red[5]+red[6]+red[7];
    float inv = rsqrtf(tot * (1.f/DD) + 1e-6f);
    int i = tid * 4;
    const float* mb = mod + b*SIXD;
    float4 wv = *(const float4*)(w + i);
    float4 sc = *(const float4*)(mb + scale_off + i);
    float4 sh = *(const float4*)(mb + shift_off + i);
    float4 o;
    o.x = fmaf(v.x*inv*wv.x, 1.f+sc.x, sh.x);
    o.y = fmaf(v.y*inv*wv.y, 1.f+sc.y, sh.y);
    o.z = fmaf(v.z*inv*wv.z, 1.f+sc.z, sh.z);
    o.w = fmaf(v.w*inv*wv.w, 1.f+sc.w, sh.w);
    *(float4*)(out + (size_t)t*DD + i) = o;
}

// ---------------- tiled SGEMM: C = A(MxK) @ B(KxN), row-major -------------
// BM=BN=128, BK=16, 256 threads, 8x8 per thread (split 4+4 for LDS.128)
__global__ void __launch_bounds__(256, 2)
sgemm_kernel(const float* __restrict__ A, const float* __restrict__ B,
             float* __restrict__ C, int M, int N, int K) {
    __shared__ float As[16][128];
    __shared__ float Bs[16][128];
    int tid  = threadIdx.x;
    int row0 = blockIdx.y * 128;
    int col0 = blockIdx.x * 128;
    int arow = tid >> 2;          // 0..63
    int acol = (tid & 3) << 2;    // 0,4,8,12
    int brow = tid >> 5;          // 0..7
    int bcol = (tid & 31) << 2;   // 0..124
    int tx = tid & 15;
    int ty = tid >> 4;

    float acc[8][8];
    #pragma unroll
    for (int i = 0; i < 8; i++)
        #pragma unroll
        for (int j = 0; j < 8; j++) acc[i][j] = 0.f;

    for (int k0 = 0; k0 < K; k0 += 16) {
        #pragma unroll
        for (int r = 0; r < 2; r++) {
            int ar = arow + (r << 6);
            float4 va = *(const float4*)(A + (size_t)(row0+ar)*K + k0 + acol);
            As[acol+0][ar] = va.x;
            As[acol+1][ar] = va.y;
            As[acol+2][ar] = va.z;
            As[acol+3][ar] = va.w;
        }
        #pragma unroll
        for (int r = 0; r < 2; r++) {
            int br = brow + (r << 3);
            int c = col0 + bcol;
            float4 vb = make_float4(0.f, 0.f, 0.f, 0.f);
            if (c < N) vb = *(const float4*)(B + (size_t)(k0+br)*N + c);
            *(float4*)&Bs[br][bcol] = vb;
        }
        __syncthreads();
        #pragma unroll
        for (int k = 0; k < 16; k++) {
            float4 a0 = *(const float4*)&As[k][ty << 2];
            float4 a1 = *(const float4*)&As[k][64 + (ty << 2)];
            float4 b0 = *(const float4*)&Bs[k][tx << 2];
            float4 b1 = *(const float4*)&Bs[k][64 + (tx << 2)];
            float a[8] = {a0.x,a0.y,a0.z,a0.w,a1.x,a1.y,a1.z,a1.w};
            float bb[8] = {b0.x,b0.y,b0.z,b0.w,b1.x,b1.y,b1.z,b1.w};
            #pragma unroll
            for (int i = 0; i < 8; i++)
                #pragma unroll
                for (int j = 0; j < 8; j++)
                    acc[i][j] = fmaf(a[i], bb[j], acc[i][j]);
        }
        __syncthreads();
    }
    #pragma unroll
    for (int i = 0; i < 8; i++) {
        int r = row0 + ((i < 4) ? (ty*4 + i) : (64 + ty*4 + i - 4));
        float* crow = C + (size_t)r * N;
        int c0 = col0 + tx*4;
        if (c0 < N)
            *(float4*)(crow + c0) = make_float4(acc[i][0], acc[i][1], acc[i][2], acc[i][3]);
        int c1 = col0 + 64 + tx*4;
        if (c1 < N)
            *(float4*)(crow + c1) = make_float4(acc[i][4], acc[i][5], acc[i][6], acc[i][7]);
    }
}

// ---------------- attention: one CTA per (b*t, head) ----------------------
// qkv row layout per token: [q(1024) | k(1024) | v(1024)], head slice h*64.
__global__ void __launch_bounds__(256, 1)
attn_kernel(const float* __restrict__ qkv, float* __restrict__ out) {
    extern __shared__ float sm[];
    float* ks = sm;                 // 256*64
    float* vs = sm + SSQ*HDIM;      // 256*64
    int bt = blockIdx.x;            // 0..63
    int h  = blockIdx.y;            // 0..15
    int i  = threadIdx.x;           // query row 0..255
    size_t base = (size_t)bt * SSQ * (3*DD);
    const float* qp = qkv + base + (size_t)i*(3*DD) + h*HDIM;
    const float* kp = qp + DD;
    const float* vp = qp + 2*DD;

    float4 q[16];
    #pragma unroll
    for (int c = 0; c < 16; c++) q[c] = ((const float4*)qp)[c];
    #pragma unroll
    for (int c = 0; c < 16; c++) ((float4*)(ks + i*HDIM))[c] = ((const float4*)kp)[c];
    #pragma unroll
    for (int c = 0; c < 16; c++) ((float4*)(vs + i*HDIM))[c] = ((const float4*)vp)[c];
    __syncthreads();

    const float scale = 0.125f;     // HD^-0.5
    // pass 1: row max
    float m = -1e30f;
    for (int j = 0; j < SSQ; j++) {
        const float4* kr = (const float4*)(ks + j*HDIM);
        float s = 0.f;
        #pragma unroll
        for (int c = 0; c < 16; c++) {
            float4 kv = kr[c];
            s = fmaf(q[c].x, kv.x, s); s = fmaf(q[c].y, kv.y, s);
            s = fmaf(q[c].z, kv.z, s); s = fmaf(q[c].w, kv.w, s);
        }
        m = fmaxf(m, s);
    }
    m *= scale;
    // pass 2: exp + weighted V accumulation
    float l = 0.f;
    float acc[64];
    #pragma unroll
    for (int c = 0; c < 64; c++) acc[c] = 0.f;
    for (int j = 0; j < SSQ; j++) {
        const float4* kr = (const float4*)(ks + j*HDIM);
        float s = 0.f;
        #pragma unroll
        for (int c = 0; c < 16; c++) {
            float4 kv = kr[c];
            s = fmaf(q[c].x, kv.x, s); s = fmaf(q[c].y, kv.y, s);
            s = fmaf(q[c].z, kv.z, s); s = fmaf(q[c].w, kv.w, s);
        }
        float p = __expf(fmaf(s, scale, -m));
        l += p;
        const float4* vr = (const float4*)(vs + j*HDIM);
        #pragma unroll
        for (int c = 0; c < 16; c++) {
            float4 vv = vr[c];
            acc[4*c+0] = fmaf(p, vv.x, acc[4*c+0]);
            acc[4*c+1] = fmaf(p, vv.y, acc[4*c+1]);
            acc[4*c+2] = fmaf(p, vv.z, acc[4*c+2]);
            acc[4*c+3] = fmaf(p, vv.w, acc[4*c+3]);
        }
    }
    float invl = 1.f / l;
    float* op = out + ((size_t)(bt*SSQ + i))*DD + h*HDIM;
    #pragma unroll
    for (int c = 0; c < 16; c++) {
        float4 o;
        o.x = acc[4*c+0]*invl; o.y = acc[4*c+1]*invl;
        o.z = acc[4*c+2]*invl; o.w = acc[4*c+3]*invl;
        ((float4*)op)[c] = o;
    }
}

// ---------------- out = x + gate[b] * h  (float4 elementwise) -------------
__global__ void resid_kernel(const float* __restrict__ x,
                             const float* __restrict__ hin,
                             const float* __restrict__ mod, int gate_off,
                             float* __restrict__ out) {
    size_t idx = (size_t)blockIdx.x * 256 + threadIdx.x;   // float4 index
    int d4 = (int)(idx & 255);             // DD/4 = 256
    int t  = (int)(idx >> 8);
    int b  = t >> 12;
    float4 g  = ((const float4*)(mod + b*SIXD + gate_off))[d4];
    float4 xv = ((const float4*)x)[idx];
    float4 hv = ((const float4*)hin)[idx];
    float4 o;
    o.x = fmaf(g.x, hv.x, xv.x);
    o.y = fmaf(g.y, hv.y, xv.y);
    o.z = fmaf(g.z, hv.z, xv.z);
    o.w = fmaf(g.w, hv.w, xv.w);
    ((float4*)out)[idx] = o;
}

// ---------------- g1 = silu(g1) * g2 --------------------------------------
__global__ void silumul_kernel(float* __restrict__ g1,
                               const float* __restrict__ g2, size_t n4) {
    size_t idx = (size_t)blockIdx.x * 256 + threadIdx.x;
    if (idx >= n4) return;
    float4 a = ((const float4*)g1)[idx];
    float4 b = ((const float4*)g2)[idx];
    float4 o;
    o.x = a.x / (1.f + __expf(-a.x)) * b.x;
    o.y = a.y / (1.f + __expf(-a.y)) * b.y;
    o.z = a.z / (1.f + __expf(-a.z)) * b.z;
    o.w = a.w / (1.f + __expf(-a.w)) * b.w;
    ((float4*)g1)[idx] = o;
}

// ---------------- launch ---------------------------------------------------
extern "C" void kernel_launch(void* const* d_in, const int* in_sizes, int n_in,
                              void* d_out, int out_size) {
    const float* x      = (const float*)d_in[0];
    const float* te     = (const float*)d_in[1];
    const float* n1w    = (const float*)d_in[2];
    const float* n2w    = (const float*)d_in[3];
    const float* qkv_w  = (const float*)d_in[4];
    const float* out_w  = (const float*)d_in[5];
    const float* w1     = (const float*)d_in[6];
    const float* w2     = (const float*)d_in[7];
    const float* w3     = (const float*)d_in[8];
    const float* mod_w  = (const float*)d_in[9];
    const float* mod_b  = (const float*)d_in[10];
    float* out = (float*)d_out;

    float *p_mod, *p_h, *p_qkv, *p_attn, *p_proj, *p_ff1, *p_ff2, *p_ffo;
    cudaGetSymbolAddress((void**)&p_mod,  g_mod);
    cudaGetSymbolAddress((void**)&p_h,    g_h);
    cudaGetSymbolAddress((void**)&p_qkv,  g_qkv);
    cudaGetSymbolAddress((void**)&p_attn, g_attn);
    cudaGetSymbolAddress((void**)&p_proj, g_proj);
    cudaGetSymbolAddress((void**)&p_ff1,  g_ff1);
    cudaGetSymbolAddress((void**)&p_ff2,  g_ff2);
    cudaGetSymbolAddress((void**)&p_ffo,  g_ffo);

    static bool attr_set = false;
    if (!attr_set) {
        cudaFuncSetAttribute(attn_kernel,
                             cudaFuncAttributeMaxDynamicSharedMemorySize,
                             2 * SSQ * HDIM * (int)sizeof(float));
        attr_set = true;
    }

    // 1. modulation vector
    mod_kernel<<<dim3(SIXD/256, BB), 256>>>(te, mod_w, mod_b, p_mod);
    // 2. h = rmsnorm(x)*(1+scale1)+shift1  (shift1@0, scale1@1024)
    norm_mod_kernel<<<TOKENS, 256>>>(x, n1w, p_mod, 0, 1024, p_h);
    // 3. qkv = h @ qkv_w
    sgemm_kernel<<<dim3(3*DD/128, TOKENS/128), 256>>>(p_h, qkv_w, p_qkv,
                                                      TOKENS, 3*DD, DD);
    // 4. attention
    attn_kernel<<<dim3(BB*TT, HH), 256, 2*SSQ*HDIM*sizeof(float)>>>(p_qkv, p_attn);
    // 5. proj = attn @ out_w
    sgemm_kernel<<<dim3(DD/128, TOKENS/128), 256>>>(p_attn, out_w, p_proj,
                                                    TOKENS, DD, DD);
    // 6. x1 = x + gate1*proj  (gate1@2048) -> d_out
    resid_kernel<<<TOKENS*DD/4/256, 256>>>(x, p_proj, p_mod, 2048, out);
    // 7. h = rmsnorm(x1)*(1+scale2)+shift2  (shift2@3072, scale2@4096)
    norm_mod_kernel<<<TOKENS, 256>>>(out, n2w, p_mod, 3072, 4096, p_h);
    // 8/9. FFN up projections
    sgemm_kernel<<<dim3((HIDDEN+127)/128, TOKENS/128), 256>>>(p_h, w1, p_ff1,
                                                              TOKENS, HIDDEN, DD);
    sgemm_kernel<<<dim3((HIDDEN+127)/128, TOKENS/128), 256>>>(p_h, w2, p_ff2,
                                                              TOKENS, HIDDEN, DD);
    // 10. ff1 = silu(ff1)*ff2
    {
        size_t n4 = (size_t)TOKENS * HIDDEN / 4;
        silumul_kernel<<<(unsigned)((n4 + 255) / 256), 256>>>(p_ff1, p_ff2, n4);
    }
    // 11. ffo = ff1 @ w3
    sgemm_kernel<<<dim3(DD/128, TOKENS/128), 256>>>(p_ff1, w3, p_ffo,
                                                    TOKENS, DD, HIDDEN);
    // 12. out = x1 + gate2*ffo  (gate2@5120)
    resid_kernel<<<TOKENS*DD/4/256, 256>>>(out, p_ffo, p_mod, 5120, out);
}

// round 3
// speedup vs baseline: 1.0764x; 1.0764x over previous
#include <cuda_runtime.h>
#include <math.h>
#include <stdint.h>

// ---------------- problem constants ----------------
#define BB 4
#define TT 16
#define SSQ 256
#define DD 1024
#define HH 16
#define HDIM 64
#define HIDDEN 2752
#define TOKENS (BB*TT*SSQ)      /* 16384 */
#define SIXD (6*DD)             /* 6144  */

// ---------------- scratch (static device globals; no runtime alloc) -------
__device__ float g_mod[BB*SIXD];
__device__ float g_h[(size_t)TOKENS*DD];
__device__ float g_qkv[(size_t)TOKENS*3*DD];
__device__ float g_attn[(size_t)TOKENS*DD];
__device__ float g_proj[(size_t)TOKENS*DD];
__device__ float g_ff1[(size_t)TOKENS*HIDDEN];
__device__ float g_ff2[(size_t)TOKENS*HIDDEN];
__device__ float g_ffo[(size_t)TOKENS*DD];

// ---------------- helpers: tf32 split + mma --------------------------------
__device__ __forceinline__ void tf32_split(float x, uint32_t& hi, uint32_t& lo) {
    uint32_t h;
    asm("cvt.rna.tf32.f32 %0, %1;" : "=r"(h) : "f"(x));
    float hf = __uint_as_float(h);
    float l = x - hf;
    uint32_t lb;
    asm("cvt.rna.tf32.f32 %0, %1;" : "=r"(lb) : "f"(l));
    hi = h; lo = lb;
}

__device__ __forceinline__ void mma_tf32(float* c,
                                         uint32_t a0, uint32_t a1, uint32_t a2, uint32_t a3,
                                         uint32_t b0, uint32_t b1) {
    asm volatile(
        "mma.sync.aligned.m16n8k8.row.col.f32.tf32.tf32.f32 "
        "{%0,%1,%2,%3},{%4,%5,%6,%7},{%8,%9},{%0,%1,%2,%3};"
        : "+f"(c[0]), "+f"(c[1]), "+f"(c[2]), "+f"(c[3])
        : "r"(a0), "r"(a1), "r"(a2), "r"(a3), "r"(b0), "r"(b1));
}

// ---------------- mod = silu(time_emb) @ mod_w + mod_b --------------------
__global__ void mod_kernel(const float* __restrict__ te,
                           const float* __restrict__ mod_w,
                           const float* __restrict__ mod_b,
                           float* __restrict__ mod) {
    __shared__ float s[DD];
    int b = blockIdx.y;
    int j = blockIdx.x * 256 + threadIdx.x;
    for (int d = threadIdx.x; d < DD; d += 256) {
        float v = te[b*DD + d];
        s[d] = v / (1.f + __expf(-v));
    }
    __syncthreads();
    float acc = mod_b[j];
    #pragma unroll 4
    for (int d = 0; d < DD; d++)
        acc = fmaf(s[d], mod_w[(size_t)d*SIXD + j], acc);
    mod[b*SIXD + j] = acc;
}

// ---------- h = rmsnorm(x, w) * (1 + scale) + shift  (one CTA per token) --
__global__ void norm_mod_kernel(const float* __restrict__ x,
                                const float* __restrict__ w,
                                const float* __restrict__ mod,
                                int shift_off, int scale_off,
                                float* __restrict__ out) {
    __shared__ float red[8];
    int t = blockIdx.x;
    int b = t >> 12;
    int tid = threadIdx.x;
    const float4* x4 = (const float4*)(x + (size_t)t*DD);
    float4 v = x4[tid];
    float ss = v.x*v.x + v.y*v.y + v.z*v.z + v.w*v.w;
    #pragma unroll
    for (int o = 16; o > 0; o >>= 1) ss += __shfl_xor_sync(0xffffffffu, ss, o);
    if ((tid & 31) == 0) red[tid >> 5] = ss;
    __syncthreads();
    float tot = red[0]+red[1]+red[2]+red[3]+red[4]+red[5]+red[6]+red[7];
    float inv = rsqrtf(tot * (1.f/DD) + 1e-6f);
    int i = tid * 4;
    const float* mb = mod + b*SIXD;
    float4 wv = *(const float4*)(w + i);
    float4 sc = *(const float4*)(mb + scale_off + i);
    float4 sh = *(const float4*)(mb + shift_off + i);
    float4 o;
    o.x = fmaf(v.x*inv*wv.x, 1.f+sc.x, sh.x);
    o.y = fmaf(v.y*inv*wv.y, 1.f+sc.y, sh.y);
    o.z = fmaf(v.z*inv*wv.z, 1.f+sc.z, sh.z);
    o.w = fmaf(v.w*inv*wv.w, 1.f+sc.w, sh.w);
    *(float4*)(out + (size_t)t*DD + i) = o;
}

// ---------------- 3xTF32 tensor-core GEMM ----------------------------------
// C(MxN) = A(MxK) @ B(KxN), row-major. BM=BN=128, BK=16, 256 threads.
// Warp grid 4(M) x 2(N): warp tile 32x64 -> 2x8 mma tiles (m16n8k8).
// Split-TF32: 3 MMAs per tile per k-step (hi*hi + lo*hi + hi*lo).
#define SMP 136   /* smem row pitch: bank stride 8 -> conflict-free frags */
__global__ void __launch_bounds__(256)
tgemm_kernel(const float* __restrict__ A, const float* __restrict__ B,
             float* __restrict__ C, int M, int N, int K) {
    __shared__ float As[2][16][SMP];
    __shared__ float Bs[2][16][SMP];

    int tid  = threadIdx.x;
    int lane = tid & 31;
    int warp = tid >> 5;
    int g = lane >> 2;      // groupID 0..7
    int t = lane & 3;       // threadID_in_group 0..3

    int row0 = blockIdx.y * 128;
    int col0 = blockIdx.x * 128;
    int warp_m = warp & 3;          // 0..3
    int warp_n = warp >> 2;         // 0..1
    int m_base = warp_m * 32;
    int n_base = warp_n * 64;

    // global load mapping
    int ar  = tid & 63;             // A row within tile (and +64)
    int acq = tid >> 6;             // A col quad 0..3
    int br  = tid >> 5;             // B row 0..7 (and +8)
    int bl  = tid & 31;             // B col quad 0..31

    const float* Ap = A + (size_t)(row0 + ar) * K + acq * 4;
    const float* Bp = B + (size_t)br * N + col0 + bl * 4;
    bool bvalid = (col0 + bl * 4 + 3) < N;

    float acc[2][8][4];
    #pragma unroll
    for (int i = 0; i < 2; i++)
        #pragma unroll
        for (int j = 0; j < 8; j++)
            #pragma unroll
            for (int c = 0; c < 4; c++) acc[i][j][c] = 0.f;

    // preload stage 0
    {
        float4 va0 = *(const float4*)(Ap);
        float4 va1 = *(const float4*)(Ap + (size_t)64 * K);
        float4 vb0 = make_float4(0.f,0.f,0.f,0.f), vb1 = vb0;
        if (bvalid) {
            vb0 = *(const float4*)(Bp);
            vb1 = *(const float4*)(Bp + (size_t)8 * N);
        }
        As[0][acq*4+0][ar] = va0.x; As[0][acq*4+1][ar] = va0.y;
        As[0][acq*4+2][ar] = va0.z; As[0][acq*4+3][ar] = va0.w;
        As[0][acq*4+0][ar+64] = va1.x; As[0][acq*4+1][ar+64] = va1.y;
        As[0][acq*4+2][ar+64] = va1.z; As[0][acq*4+3][ar+64] = va1.w;
        *(float4*)&Bs[0][br][bl*4]   = vb0;
        *(float4*)&Bs[0][br+8][bl*4] = vb1;
    }
    __syncthreads();

    int nstages = K >> 4;
    for (int s = 0; s < nstages; s++) {
        int buf = s & 1;
        float4 va0, va1, vb0, vb1;
        bool more = (s + 1) < nstages;
        if (more) {
            const float* ap = Ap + (s + 1) * 16;
            va0 = *(const float4*)(ap);
            va1 = *(const float4*)(ap + (size_t)64 * K);
            vb0 = make_float4(0.f,0.f,0.f,0.f); vb1 = vb0;
            if (bvalid) {
                const float* bp = Bp + (size_t)(s + 1) * 16 * N;
                vb0 = *(const float4*)(bp);
                vb1 = *(const float4*)(bp + (size_t)8 * N);
            }
        }

        #pragma unroll
        for (int kk = 0; kk < 16; kk += 8) {
            // load + split fragments
            uint32_t ahi[2][4], alo[2][4];
            #pragma unroll
            for (int mi = 0; mi < 2; mi++) {
                int m = m_base + 16 * mi + g;
                tf32_split(As[buf][kk + t    ][m    ], ahi[mi][0], alo[mi][0]);
                tf32_split(As[buf][kk + t    ][m + 8], ahi[mi][1], alo[mi][1]);
                tf32_split(As[buf][kk + t + 4][m    ], ahi[mi][2], alo[mi][2]);
                tf32_split(As[buf][kk + t + 4][m + 8], ahi[mi][3], alo[mi][3]);
            }
            uint32_t bhi[8][2], blo[8][2];
            #pragma unroll
            for (int ni = 0; ni < 8; ni++) {
                int n = n_base + 8 * ni + g;
                tf32_split(Bs[buf][kk + t    ][n], bhi[ni][0], blo[ni][0]);
                tf32_split(Bs[buf][kk + t + 4][n], bhi[ni][1], blo[ni][1]);
            }
            #pragma unroll
            for (int mi = 0; mi < 2; mi++)
                #pragma unroll
                for (int ni = 0; ni < 8; ni++) {
                    mma_tf32(acc[mi][ni], ahi[mi][0], ahi[mi][1], ahi[mi][2], ahi[mi][3],
                             bhi[ni][0], bhi[ni][1]);
                    mma_tf32(acc[mi][ni], alo[mi][0], alo[mi][1], alo[mi][2], alo[mi][3],
                             bhi[ni][0], bhi[ni][1]);
                    mma_tf32(acc[mi][ni], ahi[mi][0], ahi[mi][1], ahi[mi][2], ahi[mi][3],
                             blo[ni][0], blo[ni][1]);
                }
        }

        if (more) {
            int nb = buf ^ 1;
            As[nb][acq*4+0][ar] = va0.x; As[nb][acq*4+1][ar] = va0.y;
            As[nb][acq*4+2][ar] = va0.z; As[nb][acq*4+3][ar] = va0.w;
            As[nb][acq*4+0][ar+64] = va1.x; As[nb][acq*4+1][ar+64] = va1.y;
            As[nb][acq*4+2][ar+64] = va1.z; As[nb][acq*4+3][ar+64] = va1.w;
            *(float4*)&Bs[nb][br][bl*4]   = vb0;
            *(float4*)&Bs[nb][br+8][bl*4] = vb1;
            __syncthreads();
        }
    }

    // epilogue
    #pragma unroll
    for (int mi = 0; mi < 2; mi++) {
        #pragma unroll
        for (int ni = 0; ni < 8; ni++) {
            int ctile = col0 + n_base + 8 * ni;
            if (ctile >= N) continue;
            int r = row0 + m_base + 16 * mi + g;
            int c = ctile + 2 * t;
            *(float2*)(C + (size_t)r * N + c) =
                make_float2(acc[mi][ni][0], acc[mi][ni][1]);
            *(float2*)(C + (size_t)(r + 8) * N + c) =
                make_float2(acc[mi][ni][2], acc[mi][ni][3]);
        }
    }
}

// ---------------- attention: one CTA per (b*t, head), online softmax ------
__global__ void __launch_bounds__(256, 1)
attn_kernel(const float* __restrict__ qkv, float* __restrict__ out) {
    extern __shared__ float sm[];
    float* ks = sm;                 // 256*64
    float* vs = sm + SSQ*HDIM;      // 256*64
    int bt = blockIdx.x;
    int h  = blockIdx.y;
    int i  = threadIdx.x;
    size_t base = (size_t)bt * SSQ * (3*DD);
    const float* qp = qkv + base + (size_t)i*(3*DD) + h*HDIM;
    const float* kp = qp + DD;
    const float* vp = qp + 2*DD;

    float4 q[16];
    #pragma unroll
    for (int c = 0; c < 16; c++) q[c] = ((const float4*)qp)[c];
    #pragma unroll
    for (int c = 0; c < 16; c++) ((float4*)(ks + i*HDIM))[c] = ((const float4*)kp)[c];
    #pragma unroll
    for (int c = 0; c < 16; c++) ((float4*)(vs + i*HDIM))[c] = ((const float4*)vp)[c];
    __syncthreads();

    const float scale = 0.125f;
    float m = -1e30f, l = 0.f;
    float acc[64];
    #pragma unroll
    for (int c = 0; c < 64; c++) acc[c] = 0.f;

    for (int j = 0; j < SSQ; j++) {
        const float4* kr = (const float4*)(ks + j*HDIM);
        float s = 0.f;
        #pragma unroll
        for (int c = 0; c < 16; c++) {
            float4 kv = kr[c];
            s = fmaf(q[c].x, kv.x, s); s = fmaf(q[c].y, kv.y, s);
            s = fmaf(q[c].z, kv.z, s); s = fmaf(q[c].w, kv.w, s);
        }
        s *= scale;
        float p;
        if (s > m) {
            float cfac = __expf(m - s);   // 0 on first iteration
            l *= cfac;
            #pragma unroll
            for (int c = 0; c < 64; c++) acc[c] *= cfac;
            m = s;
            p = 1.f;
        } else {
            p = __expf(s - m);
        }
        l += p;
        const float4* vr = (const float4*)(vs + j*HDIM);
        #pragma unroll
        for (int c = 0; c < 16; c++) {
            float4 vv = vr[c];
            acc[4*c+0] = fmaf(p, vv.x, acc[4*c+0]);
            acc[4*c+1] = fmaf(p, vv.y, acc[4*c+1]);
            acc[4*c+2] = fmaf(p, vv.z, acc[4*c+2]);
            acc[4*c+3] = fmaf(p, vv.w, acc[4*c+3]);
        }
    }
    float invl = 1.f / l;
    float* op = out + ((size_t)(bt*SSQ + i))*DD + h*HDIM;
    #pragma unroll
    for (int c = 0; c < 16; c++) {
        float4 o;
        o.x = acc[4*c+0]*invl; o.y = acc[4*c+1]*invl;
        o.z = acc[4*c+2]*invl; o.w = acc[4*c+3]*invl;
        ((float4*)op)[c] = o;
    }
}

// ---------------- out = x + gate[b] * h  (float4 elementwise) -------------
__global__ void resid_kernel(const float* __restrict__ x,
                             const float* __restrict__ hin,
                             const float* __restrict__ mod, int gate_off,
                             float* __restrict__ out) {
    size_t idx = (size_t)blockIdx.x * 256 + threadIdx.x;
    int d4 = (int)(idx & 255);
    int t  = (int)(idx >> 8);
    int b  = t >> 12;
    float4 g  = ((const float4*)(mod + b*SIXD + gate_off))[d4];
    float4 xv = ((const float4*)x)[idx];
    float4 hv = ((const float4*)hin)[idx];
    float4 o;
    o.x = fmaf(g.x, hv.x, xv.x);
    o.y = fmaf(g.y, hv.y, xv.y);
    o.z = fmaf(g.z, hv.z, xv.z);
    o.w = fmaf(g.w, hv.w, xv.w);
    ((float4*)out)[idx] = o;
}

// ---------------- g1 = silu(g1) * g2 --------------------------------------
__global__ void silumul_kernel(float* __restrict__ g1,
                               const float* __restrict__ g2, size_t n4) {
    size_t idx = (size_t)blockIdx.x * 256 + threadIdx.x;
    if (idx >= n4) return;
    float4 a = ((const float4*)g1)[idx];
    float4 b = ((const float4*)g2)[idx];
    float4 o;
    o.x = a.x / (1.f + __expf(-a.x)) * b.x;
    o.y = a.y / (1.f + __expf(-a.y)) * b.y;
    o.z = a.z / (1.f + __expf(-a.z)) * b.z;
    o.w = a.w / (1.f + __expf(-a.w)) * b.w;
    ((float4*)g1)[idx] = o;
}

// ---------------- launch ---------------------------------------------------
extern "C" void kernel_launch(void* const* d_in, const int* in_sizes, int n_in,
                              void* d_out, int out_size) {
    const float* x      = (const float*)d_in[0];
    const float* te     = (const float*)d_in[1];
    const float* n1w    = (const float*)d_in[2];
    const float* n2w    = (const float*)d_in[3];
    const float* qkv_w  = (const float*)d_in[4];
    const float* out_w  = (const float*)d_in[5];
    const float* w1     = (const float*)d_in[6];
    const float* w2     = (const float*)d_in[7];
    const float* w3     = (const float*)d_in[8];
    const float* mod_w  = (const float*)d_in[9];
    const float* mod_b  = (const float*)d_in[10];
    float* out = (float*)d_out;

    float *p_mod, *p_h, *p_qkv, *p_attn, *p_proj, *p_ff1, *p_ff2, *p_ffo;
    cudaGetSymbolAddress((void**)&p_mod,  g_mod);
    cudaGetSymbolAddress((void**)&p_h,    g_h);
    cudaGetSymbolAddress((void**)&p_qkv,  g_qkv);
    cudaGetSymbolAddress((void**)&p_attn, g_attn);
    cudaGetSymbolAddress((void**)&p_proj, g_proj);
    cudaGetSymbolAddress((void**)&p_ff1,  g_ff1);
    cudaGetSymbolAddress((void**)&p_ff2,  g_ff2);
    cudaGetSymbolAddress((void**)&p_ffo,  g_ffo);

    static bool attr_set = false;
    if (!attr_set) {
        cudaFuncSetAttribute(attn_kernel,
                             cudaFuncAttributeMaxDynamicSharedMemorySize,
                             2 * SSQ * HDIM * (int)sizeof(float));
        attr_set = true;
    }

    // 1. modulation vector
    mod_kernel<<<dim3(SIXD/256, BB), 256>>>(te, mod_w, mod_b, p_mod);
    // 2. h = rmsnorm(x)*(1+scale1)+shift1
    norm_mod_kernel<<<TOKENS, 256>>>(x, n1w, p_mod, 0, 1024, p_h);
    // 3. qkv = h @ qkv_w
    tgemm_kernel<<<dim3(3*DD/128, TOKENS/128), 256>>>(p_h, qkv_w, p_qkv,
                                                      TOKENS, 3*DD, DD);
    // 4. attention
    attn_kernel<<<dim3(BB*TT, HH), 256, 2*SSQ*HDIM*sizeof(float)>>>(p_qkv, p_attn);
    // 5. proj = attn @ out_w
    tgemm_kernel<<<dim3(DD/128, TOKENS/128), 256>>>(p_attn, out_w, p_proj,
                                                    TOKENS, DD, DD);
    // 6. x1 = x + gate1*proj -> d_out
    resid_kernel<<<TOKENS*DD/4/256, 256>>>(x, p_proj, p_mod, 2048, out);
    // 7. h = rmsnorm(x1)*(1+scale2)+shift2
    norm_mod_kernel<<<TOKENS, 256>>>(out, n2w, p_mod, 3072, 4096, p_h);
    // 8/9. FFN up projections
    tgemm_kernel<<<dim3((HIDDEN+127)/128, TOKENS/128), 256>>>(p_h, w1, p_ff1,
                                                              TOKENS, HIDDEN, DD);
    tgemm_kernel<<<dim3((HIDDEN+127)/128, TOKENS/128), 256>>>(p_h, w2, p_ff2,
                                                              TOKENS, HIDDEN, DD);
    // 10. ff1 = silu(ff1)*ff2
    {
        size_t n4 = (size_t)TOKENS * HIDDEN / 4;
        silumul_kernel<<<(unsigned)((n4 + 255) / 256), 256>>>(p_ff1, p_ff2, n4);
    }
    // 11. ffo = ff1 @ w3
    tgemm_kernel<<<dim3(DD/128, TOKENS/128), 256>>>(p_ff1, w3, p_ffo,
                                                    TOKENS, DD, HIDDEN);
    // 12. out = x1 + gate2*ffo
    resid_kernel<<<TOKENS*DD/4/256, 256>>>(out, p_ffo, p_mod, 5120, out);
}

// round 12
// speedup vs baseline: 1.9852x; 1.8442x over previous
#include <cuda_runtime.h>
#include <cuda_bf16.h>
#include <math.h>
#include <stdint.h>

// ---------------- problem constants ----------------
#define BB 4
#define TT 16
#define SSQ 256
#define DD 1024
#define HH 16
#define HDIM 64
#define HIDDEN 2752
#define HPAD 2816               /* HIDDEN padded to 128 multiple */
#define TOKENS (BB*TT*SSQ)      /* 16384 */
#define SIXD (6*DD)             /* 6144  */

// ---------------- scratch (static device globals; no runtime alloc) -------
__device__ float g_mod[BB*SIXD];
__device__ __nv_bfloat16 g_hh[(size_t)TOKENS*DD];
__device__ __nv_bfloat16 g_hl[(size_t)TOKENS*DD];
__device__ float g_qkv[(size_t)TOKENS*3*DD];
__device__ __nv_bfloat16 g_ah[(size_t)TOKENS*DD];
__device__ __nv_bfloat16 g_al[(size_t)TOKENS*DD];
__device__ float g_proj[(size_t)TOKENS*DD];
__device__ float g_ff1[(size_t)TOKENS*HIDDEN];
__device__ float g_ff2[(size_t)TOKENS*HIDDEN];
__device__ __nv_bfloat16 g_gh[(size_t)TOKENS*HIDDEN];
__device__ __nv_bfloat16 g_gl[(size_t)TOKENS*HIDDEN];
__device__ float g_ffo[(size_t)TOKENS*DD];
// transposed + split weights  Wt[n][k]
__device__ __nv_bfloat16 g_wqh[(size_t)3*DD*DD], g_wql[(size_t)3*DD*DD];
__device__ __nv_bfloat16 g_woh[(size_t)DD*DD],  g_wol[(size_t)DD*DD];
__device__ __nv_bfloat16 g_w1h[(size_t)HPAD*DD], g_w1l[(size_t)HPAD*DD];
__device__ __nv_bfloat16 g_w2h[(size_t)HPAD*DD], g_w2l[(size_t)HPAD*DD];
__device__ __nv_bfloat16 g_w3h[(size_t)DD*HIDDEN], g_w3l[(size_t)DD*HIDDEN];

// ---------------- helpers ---------------------------------------------------
__device__ __forceinline__ uint32_t smem_u32(const void* p) {
    return (uint32_t)__cvta_generic_to_shared(p);
}
__device__ __forceinline__ void cp16(uint32_t dst, const void* src) {
    asm volatile("cp.async.cg.shared.global [%0], [%1], 16;"
                 :: "r"(dst), "l"(src) : "memory");
}
__device__ __forceinline__ void cp_commit() {
    asm volatile("cp.async.commit_group;" ::: "memory");
}
__device__ __forceinline__ void cp_wait0() {
    asm volatile("cp.async.wait_group 0;" ::: "memory");
}
__device__ __forceinline__ void ldm_x4(uint32_t* r, uint32_t addr) {
    asm volatile("ldmatrix.sync.aligned.m8n8.x4.shared.b16 {%0,%1,%2,%3}, [%4];"
                 : "=r"(r[0]), "=r"(r[1]), "=r"(r[2]), "=r"(r[3]) : "r"(addr));
}
__device__ __forceinline__ void mma_bf16(float* c, const uint32_t* a,
                                         uint32_t b0, uint32_t b1) {
    asm volatile(
        "mma.sync.aligned.m16n8k16.row.col.f32.bf16.bf16.f32 "
        "{%0,%1,%2,%3},{%4,%5,%6,%7},{%8,%9},{%0,%1,%2,%3};"
        : "+f"(c[0]), "+f"(c[1]), "+f"(c[2]), "+f"(c[3])
        : "r"(a[0]), "r"(a[1]), "r"(a[2]), "r"(a[3]), "r"(b0), "r"(b1));
}
__device__ __forceinline__ void split_store2(__nv_bfloat16* hi, __nv_bfloat16* lo,
                                             size_t off, float a, float b) {
    __nv_bfloat16 ha = __float2bfloat16(a), hb = __float2bfloat16(b);
    __nv_bfloat16 la = __float2bfloat16(a - __bfloat162float(ha));
    __nv_bfloat16 lb = __float2bfloat16(b - __bfloat162float(hb));
    *(__nv_bfloat162*)(hi + off) = __halves2bfloat162(ha, hb);
    *(__nv_bfloat162*)(lo + off) = __halves2bfloat162(la, lb);
}

// ---------------- weight prep: transpose + bf16 split ----------------------
// W [K,N] row-major  ->  Thi/Tlo [Npad, K]  (rows >= N zero-filled)
__global__ void wprep_kernel(const float* __restrict__ W, int K, int N, int Npad,
                             __nv_bfloat16* __restrict__ Thi,
                             __nv_bfloat16* __restrict__ Tlo) {
    __shared__ float t[32][33];
    int n0 = blockIdx.x * 32, k0 = blockIdx.y * 32;
    int tx = threadIdx.x, ty = threadIdx.y;
    #pragma unroll
    for (int i = 0; i < 32; i += 8) {
        int n = n0 + tx;
        t[ty + i][tx] = (n < N) ? W[(size_t)(k0 + ty + i) * N + n] : 0.f;
    }
    __syncthreads();
    #pragma unroll
    for (int i = 0; i < 32; i += 8) {
        int n = n0 + ty + i;
        if (n < Npad) {
            float v = t[tx][ty + i];
            __nv_bfloat16 h = __float2bfloat16(v);
            Thi[(size_t)n * K + k0 + tx] = h;
            Tlo[(size_t)n * K + k0 + tx] = __float2bfloat16(v - __bfloat162float(h));
        }
    }
}

// ---------------- bf16 split-GEMM via mma.sync + cp.async ------------------
// C[M,Ntrue] = A[M,K] @ Bt[N,K]^T, 3-term bf16 split.
// CTA 128x128, BK=32, 256 thr (8 warps: 4m x 2n, warp tile 32x64).
#define PITCH 40                /* bf16 elems per smem row (32 + 8 pad)   */
#define ARR_B (128*PITCH*2)     /* 10240 bytes per array                  */
#define STAGE_B (4*ARR_B)       /* Ah, Al, Bh, Bl                          */
#define GEMM_SMEM (2*STAGE_B)   /* 81920                                   */
__global__ void __launch_bounds__(256, 2)
bgemm_kernel(const __nv_bfloat16* __restrict__ Ahi, const __nv_bfloat16* __restrict__ Alo,
             const __nv_bfloat16* __restrict__ Bhi, const __nv_bfloat16* __restrict__ Blo,
             float* __restrict__ C, int Ntrue, int K) {
    extern __shared__ __align__(128) char smem[];
    const uint32_t sbase = smem_u32(smem);
    const int tid = threadIdx.x, lane = tid & 31, warp = tid >> 5;
    const int wm = warp & 3, wn = warp >> 2;
    const int row0 = blockIdx.y * 128, col0 = blockIdx.x * 128;

    // cp.async mapping: chunk = 16B = 8 bf16. 128 rows x 4 chunks per array.
    const int crow = tid >> 1;                  // 0..127
    const int coff = (tid & 1) * 2;             // chunk pair 0 or 2

    auto load_stage = [&](int k0, int buf) {
        uint32_t sb = sbase + buf * STAGE_B;
        const __nv_bfloat16* ga = Ahi + (size_t)(row0 + crow) * K + k0 + coff * 8;
        const __nv_bfloat16* gal = Alo + (size_t)(row0 + crow) * K + k0 + coff * 8;
        const __nv_bfloat16* gb = Bhi + (size_t)(col0 + crow) * K + k0 + coff * 8;
        const __nv_bfloat16* gbl = Blo + (size_t)(col0 + crow) * K + k0 + coff * 8;
        uint32_t sd = sb + crow * (PITCH*2) + coff * 16;
        cp16(sd,             ga);
        cp16(sd + 16,        ga + 8);
        cp16(sd + ARR_B,     gal);
        cp16(sd + ARR_B+16,  gal + 8);
        cp16(sd + 2*ARR_B,    gb);
        cp16(sd + 2*ARR_B+16, gb + 8);
        cp16(sd + 3*ARR_B,    gbl);
        cp16(sd + 3*ARR_B+16, gbl + 8);
        cp_commit();
    };

    float acc[2][8][4];
    #pragma unroll
    for (int i = 0; i < 2; i++)
        #pragma unroll
        for (int j = 0; j < 8; j++)
            #pragma unroll
            for (int c = 0; c < 4; c++) acc[i][j][c] = 0.f;

    const int S = K >> 5;
    load_stage(0, 0);

    // ldmatrix lane addressing (within tile, element coords)
    const int a_r = (lane & 7) + ((lane >> 3) & 1) * 8;   // row within m16
    const int a_c = ((lane >> 4) & 1) * 8;                // k half
    const int b_r = (lane & 7) + ((lane >> 4) & 1) * 8;   // n within n16
    const int b_c = ((lane >> 3) & 1) * 8;                // k half

    for (int s = 0; s < S; s++) {
        const int buf = s & 1;
        cp_wait0();
        __syncthreads();
        if (s + 1 < S) load_stage((s + 1) << 5, buf ^ 1);

        const uint32_t sb = sbase + buf * STAGE_B;
        #pragma unroll
        for (int k16 = 0; k16 < 32; k16 += 16) {
            uint32_t Ah[2][4], Al[2][4];
            #pragma unroll
            for (int mi = 0; mi < 2; mi++) {
                uint32_t ad = sb + (wm*32 + mi*16 + a_r) * (PITCH*2) + (k16 + a_c) * 2;
                ldm_x4(Ah[mi], ad);
                ldm_x4(Al[mi], ad + ARR_B);
            }
            #pragma unroll
            for (int nj = 0; nj < 4; nj++) {
                uint32_t Bh[4], Bl[4];
                uint32_t bd = sb + 2*ARR_B + (wn*64 + nj*16 + b_r) * (PITCH*2)
                            + (k16 + b_c) * 2;
                ldm_x4(Bh, bd);
                ldm_x4(Bl, bd + ARR_B);
                #pragma unroll
                for (int mi = 0; mi < 2; mi++) {
                    #pragma unroll
                    for (int t = 0; t < 2; t++) {
                        float* c = acc[mi][2*nj + t];
                        mma_bf16(c, Ah[mi], Bh[2*t], Bh[2*t+1]);
                        mma_bf16(c, Al[mi], Bh[2*t], Bh[2*t+1]);
                        mma_bf16(c, Ah[mi], Bl[2*t], Bl[2*t+1]);
                    }
                }
            }
        }
        __syncthreads();
    }

    // epilogue
    const int erow = row0 + wm*32 + (lane >> 2);
    const int ecol0 = col0 + wn*64 + 2*(lane & 3);
    #pragma unroll
    for (int mi = 0; mi < 2; mi++) {
        #pragma unroll
        for (int ni = 0; ni < 8; ni++) {
            int c = ecol0 + ni*8;
            if (c < Ntrue) {
                float* cp0 = C + (size_t)(erow + mi*16) * Ntrue + c;
                *(float2*)cp0 = make_float2(acc[mi][ni][0], acc[mi][ni][1]);
                *(float2*)(cp0 + (size_t)8 * Ntrue) =
                    make_float2(acc[mi][ni][2], acc[mi][ni][3]);
            }
        }
    }
}

// ---------------- mod = silu(time_emb) @ mod_w + mod_b --------------------
__global__ void mod_kernel(const float* __restrict__ te,
                           const float* __restrict__ mod_w,
                           const float* __restrict__ mod_b,
                           float* __restrict__ mod) {
    __shared__ float s[DD];
    int b = blockIdx.y;
    int j = blockIdx.x * 256 + threadIdx.x;
    for (int d = threadIdx.x; d < DD; d += 256) {
        float v = te[b*DD + d];
        s[d] = v / (1.f + __expf(-v));
    }
    __syncthreads();
    float acc = mod_b[j];
    #pragma unroll 4
    for (int d = 0; d < DD; d++)
        acc = fmaf(s[d], mod_w[(size_t)d*SIXD + j], acc);
    mod[b*SIXD + j] = acc;
}

// ---------- rmsnorm*(1+scale)+shift -> bf16 hi/lo  (one CTA per token) ----
__global__ void norm_mod_kernel(const float* __restrict__ x,
                                const float* __restrict__ w,
                                const float* __restrict__ mod,
                                int shift_off, int scale_off,
                                __nv_bfloat16* __restrict__ ohi,
                                __nv_bfloat16* __restrict__ olo) {
    __shared__ float red[8];
    int t = blockIdx.x;
    int b = t >> 12;
    int tid = threadIdx.x;
    const float4* x4 = (const float4*)(x + (size_t)t*DD);
    float4 v = x4[tid];
    float ss = v.x*v.x + v.y*v.y + v.z*v.z + v.w*v.w;
    #pragma unroll
    for (int o = 16; o > 0; o >>= 1) ss += __shfl_xor_sync(0xffffffffu, ss, o);
    if ((tid & 31) == 0) red[tid >> 5] = ss;
    __syncthreads();
    float tot = red[0]+red[1]+red[2]+red[3]+red[4]+red[5]+red[6]+red[7];
    float inv = rsqrtf(tot * (1.f/DD) + 1e-6f);
    int i = tid * 4;
    const float* mb = mod + b*SIXD;
    float4 wv = *(const float4*)(w + i);
    float4 sc = *(const float4*)(mb + scale_off + i);
    float4 sh = *(const float4*)(mb + shift_off + i);
    float o0 = fmaf(v.x*inv*wv.x, 1.f+sc.x, sh.x);
    float o1 = fmaf(v.y*inv*wv.y, 1.f+sc.y, sh.y);
    float o2 = fmaf(v.z*inv*wv.z, 1.f+sc.z, sh.z);
    float o3 = fmaf(v.w*inv*wv.w, 1.f+sc.w, sh.w);
    size_t off = (size_t)t*DD + i;
    split_store2(ohi, olo, off,     o0, o1);
    split_store2(ohi, olo, off + 2, o2, o3);
}

// ---------------- attention (online softmax), bf16 hi/lo out --------------
__global__ void __launch_bounds__(256, 1)
attn_kernel(const float* __restrict__ qkv,
            __nv_bfloat16* __restrict__ ohi, __nv_bfloat16* __restrict__ olo) {
    extern __shared__ float sm[];
    float* ks = sm;
    float* vs = sm + SSQ*HDIM;
    int bt = blockIdx.x;
    int h  = blockIdx.y;
    int i  = threadIdx.x;
    size_t base = (size_t)bt * SSQ * (3*DD);
    const float* qp = qkv + base + (size_t)i*(3*DD) + h*HDIM;
    const float* kp = qp + DD;
    const float* vp = qp + 2*DD;

    float4 q[16];
    #pragma unroll
    for (int c = 0; c < 16; c++) q[c] = ((const float4*)qp)[c];
    #pragma unroll
    for (int c = 0; c < 16; c++) ((float4*)(ks + i*HDIM))[c] = ((const float4*)kp)[c];
    #pragma unroll
    for (int c = 0; c < 16; c++) ((float4*)(vs + i*HDIM))[c] = ((const float4*)vp)[c];
    __syncthreads();

    const float scale = 0.125f;
    float m = -1e30f, l = 0.f;
    float acc[64];
    #pragma unroll
    for (int c = 0; c < 64; c++) acc[c] = 0.f;

    for (int j = 0; j < SSQ; j++) {
        const float4* kr = (const float4*)(ks + j*HDIM);
        float s = 0.f;
        #pragma unroll
        for (int c = 0; c < 16; c++) {
            float4 kv = kr[c];
            s = fmaf(q[c].x, kv.x, s); s = fmaf(q[c].y, kv.y, s);
            s = fmaf(q[c].z, kv.z, s); s = fmaf(q[c].w, kv.w, s);
        }
        s *= scale;
        float p;
        if (s > m) {
            float cfac = __expf(m - s);
            l *= cfac;
            #pragma unroll
            for (int c = 0; c < 64; c++) acc[c] *= cfac;
            m = s;
            p = 1.f;
        } else {
            p = __expf(s - m);
        }
        l += p;
        const float4* vr = (const float4*)(vs + j*HDIM);
        #pragma unroll
        for (int c = 0; c < 16; c++) {
            float4 vv = vr[c];
            acc[4*c+0] = fmaf(p, vv.x, acc[4*c+0]);
            acc[4*c+1] = fmaf(p, vv.y, acc[4*c+1]);
            acc[4*c+2] = fmaf(p, vv.z, acc[4*c+2]);
            acc[4*c+3] = fmaf(p, vv.w, acc[4*c+3]);
        }
    }
    float invl = 1.f / l;
    size_t off = (size_t)(bt*SSQ + i)*DD + h*HDIM;
    #pragma unroll
    for (int c = 0; c < 32; c++)
        split_store2(ohi, olo, off + 2*c, acc[2*c]*invl, acc[2*c+1]*invl);
}

// ---------------- out = x + gate[b] * h  ----------------------------------
__global__ void resid_kernel(const float* __restrict__ x,
                             const float* __restrict__ hin,
                             const float* __restrict__ mod, int gate_off,
                             float* __restrict__ out) {
    size_t idx = (size_t)blockIdx.x * 256 + threadIdx.x;
    int d4 = (int)(idx & 255);
    int t  = (int)(idx >> 8);
    int b  = t >> 12;
    float4 g  = ((const float4*)(mod + b*SIXD + gate_off))[d4];
    float4 xv = ((const float4*)x)[idx];
    float4 hv = ((const float4*)hin)[idx];
    float4 o;
    o.x = fmaf(g.x, hv.x, xv.x);
    o.y = fmaf(g.y, hv.y, xv.y);
    o.z = fmaf(g.z, hv.z, xv.z);
    o.w = fmaf(g.w, hv.w, xv.w);
    ((float4*)out)[idx] = o;
}

// ---------------- g = silu(a)*b -> bf16 hi/lo ------------------------------
__global__ void silumul_kernel(const float* __restrict__ a4,
                               const float* __restrict__ b4,
                               __nv_bfloat16* __restrict__ ghi,
                               __nv_bfloat16* __restrict__ glo, size_t n4) {
    size_t idx = (size_t)blockIdx.x * 256 + threadIdx.x;
    if (idx >= n4) return;
    float4 a = ((const float4*)a4)[idx];
    float4 b = ((const float4*)b4)[idx];
    float o0 = a.x / (1.f + __expf(-a.x)) * b.x;
    float o1 = a.y / (1.f + __expf(-a.y)) * b.y;
    float o2 = a.z / (1.f + __expf(-a.z)) * b.z;
    float o3 = a.w / (1.f + __expf(-a.w)) * b.w;
    split_store2(ghi, glo, idx*4,     o0, o1);
    split_store2(ghi, glo, idx*4 + 2, o2, o3);
}

// ---------------- launch ---------------------------------------------------
extern "C" void kernel_launch(void* const* d_in, const int* in_sizes, int n_in,
                              void* d_out, int out_size) {
    const float* x      = (const float*)d_in[0];
    const float* te     = (const float*)d_in[1];
    const float* n1w    = (const float*)d_in[2];
    const float* n2w    = (const float*)d_in[3];
    const float* qkv_w  = (const float*)d_in[4];
    const float* out_w  = (const float*)d_in[5];
    const float* w1     = (const float*)d_in[6];
    const float* w2     = (const float*)d_in[7];
    const float* w3     = (const float*)d_in[8];
    const float* mod_w  = (const float*)d_in[9];
    const float* mod_b  = (const float*)d_in[10];
    float* out = (float*)d_out;

    float *p_mod, *p_qkv, *p_proj, *p_ff1, *p_ff2, *p_ffo;
    __nv_bfloat16 *p_hh, *p_hl, *p_ah, *p_al, *p_gh, *p_gl;
    __nv_bfloat16 *p_wqh, *p_wql, *p_woh, *p_wol, *p_w1h, *p_w1l,
                  *p_w2h, *p_w2l, *p_w3h, *p_w3l;
    cudaGetSymbolAddress((void**)&p_mod,  g_mod);
    cudaGetSymbolAddress((void**)&p_hh,   g_hh);
    cudaGetSymbolAddress((void**)&p_hl,   g_hl);
    cudaGetSymbolAddress((void**)&p_qkv,  g_qkv);
    cudaGetSymbolAddress((void**)&p_ah,   g_ah);
    cudaGetSymbolAddress((void**)&p_al,   g_al);
    cudaGetSymbolAddress((void**)&p_proj, g_proj);
    cudaGetSymbolAddress((void**)&p_ff1,  g_ff1);
    cudaGetSymbolAddress((void**)&p_ff2,  g_ff2);
    cudaGetSymbolAddress((void**)&p_gh,   g_gh);
    cudaGetSymbolAddress((void**)&p_gl,   g_gl);
    cudaGetSymbolAddress((void**)&p_ffo,  g_ffo);
    cudaGetSymbolAddress((void**)&p_wqh,  g_wqh);
    cudaGetSymbolAddress((void**)&p_wql,  g_wql);
    cudaGetSymbolAddress((void**)&p_woh,  g_woh);
    cudaGetSymbolAddress((void**)&p_wol,  g_wol);
    cudaGetSymbolAddress((void**)&p_w1h,  g_w1h);
    cudaGetSymbolAddress((void**)&p_w1l,  g_w1l);
    cudaGetSymbolAddress((void**)&p_w2h,  g_w2h);
    cudaGetSymbolAddress((void**)&p_w2l,  g_w2l);
    cudaGetSymbolAddress((void**)&p_w3h,  g_w3h);
    cudaGetSymbolAddress((void**)&p_w3l,  g_w3l);

    static bool attr_set = false;
    if (!attr_set) {
        cudaFuncSetAttribute(attn_kernel,
                             cudaFuncAttributeMaxDynamicSharedMemorySize,
                             2 * SSQ * HDIM * (int)sizeof(float));
        cudaFuncSetAttribute(bgemm_kernel,
                             cudaFuncAttributeMaxDynamicSharedMemorySize,
                             GEMM_SMEM);
        attr_set = true;
    }

    dim3 tp(32, 8);
    // weight prep: transpose + split
    wprep_kernel<<<dim3(3*DD/32, DD/32), tp>>>(qkv_w, DD, 3*DD, 3*DD, p_wqh, p_wql);
    wprep_kernel<<<dim3(DD/32, DD/32), tp>>>(out_w, DD, DD, DD, p_woh, p_wol);
    wprep_kernel<<<dim3(HPAD/32, DD/32), tp>>>(w1, DD, HIDDEN, HPAD, p_w1h, p_w1l);
    wprep_kernel<<<dim3(HPAD/32, DD/32), tp>>>(w2, DD, HIDDEN, HPAD, p_w2h, p_w2l);
    wprep_kernel<<<dim3(DD/32, HIDDEN/32), tp>>>(w3, HIDDEN, DD, DD, p_w3h, p_w3l);

    // 1. modulation vector
    mod_kernel<<<dim3(SIXD/256, BB), 256>>>(te, mod_w, mod_b, p_mod);
    // 2. h = rmsnorm(x)*(1+scale1)+shift1 -> bf16 hi/lo
    norm_mod_kernel<<<TOKENS, 256>>>(x, n1w, p_mod, 0, 1024, p_hh, p_hl);
    // 3. qkv = h @ qkv_w
    bgemm_kernel<<<dim3(3*DD/128, TOKENS/128), 256, GEMM_SMEM>>>(
        p_hh, p_hl, p_wqh, p_wql, p_qkv, 3*DD, DD);
    // 4. attention -> bf16 hi/lo
    attn_kernel<<<dim3(BB*TT, HH), 256, 2*SSQ*HDIM*sizeof(float)>>>(p_qkv, p_ah, p_al);
    // 5. proj = attn @ out_w
    bgemm_kernel<<<dim3(DD/128, TOKENS/128), 256, GEMM_SMEM>>>(
        p_ah, p_al, p_woh, p_wol, p_proj, DD, DD);
    // 6. x1 = x + gate1*proj -> d_out
    resid_kernel<<<TOKENS*DD/4/256, 256>>>(x, p_proj, p_mod, 2048, out);
    // 7. h = rmsnorm(x1)*(1+scale2)+shift2 -> bf16 hi/lo
    norm_mod_kernel<<<TOKENS, 256>>>(out, n2w, p_mod, 3072, 4096, p_hh, p_hl);
    // 8/9. FFN up projections
    bgemm_kernel<<<dim3(HPAD/128, TOKENS/128), 256, GEMM_SMEM>>>(
        p_hh, p_hl, p_w1h, p_w1l, p_ff1, HIDDEN, DD);
    bgemm_kernel<<<dim3(HPAD/128, TOKENS/128), 256, GEMM_SMEM>>>(
        p_hh, p_hl, p_w2h, p_w2l, p_ff2, HIDDEN, DD);
    // 10. g = silu(ff1)*ff2 -> bf16 hi/lo
    {
        size_t n4 = (size_t)TOKENS * HIDDEN / 4;
        silumul_kernel<<<(unsigned)((n4 + 255) / 256), 256>>>(p_ff1, p_ff2,
                                                              p_gh, p_gl, n4);
    }
    // 11. ffo = g @ w3
    bgemm_kernel<<<dim3(DD/128, TOKENS/128), 256, GEMM_SMEM>>>(
        p_gh, p_gl, p_w3h, p_w3l, p_ffo, DD, HIDDEN);
    // 12. out = x1 + gate2*ffo
    resid_kernel<<<TOKENS*DD/4/256, 256>>>(out, p_ffo, p_mod, 5120, out);
}

// round 17
// speedup vs baseline: 2.6397x; 1.3297x over previous
#include <cuda_runtime.h>
#include <cuda_fp16.h>
#include <math.h>
#include <stdint.h>

// ---------------- problem constants ----------------
#define BB 4
#define TT 16
#define SSQ 256
#define DD 1024
#define HH 16
#define HDIM 64
#define HIDDEN 2752
#define HPAD 2816               /* HIDDEN padded to 128 multiple */
#define TOKENS (BB*TT*SSQ)      /* 16384 */
#define SIXD (6*DD)             /* 6144  */

// ---------------- scratch (static device globals; no runtime alloc) -------
__device__ float g_mod[BB*SIXD];
__device__ __half g_hh[(size_t)TOKENS*DD];
__device__ __half g_hl[(size_t)TOKENS*DD];
__device__ float g_qkv[(size_t)TOKENS*3*DD];
__device__ __half g_ah[(size_t)TOKENS*DD];
__device__ __half g_al[(size_t)TOKENS*DD];
__device__ float g_proj[(size_t)TOKENS*DD];
__device__ float g_ff1[(size_t)TOKENS*HIDDEN];
__device__ float g_ff2[(size_t)TOKENS*HIDDEN];
__device__ __half g_gh[(size_t)TOKENS*HIDDEN];
__device__ __half g_gl[(size_t)TOKENS*HIDDEN];
__device__ float g_ffo[(size_t)TOKENS*DD];
// transposed fp16 weights  Wt[n][k]
__device__ __half g_wq[(size_t)3*DD*DD];
__device__ __half g_wo[(size_t)DD*DD];
__device__ __half g_w1[(size_t)HPAD*DD];
__device__ __half g_w2[(size_t)HPAD*DD];
__device__ __half g_w3[(size_t)DD*HIDDEN];

// ---------------- helpers ---------------------------------------------------
__device__ __forceinline__ uint32_t smem_u32(const void* p) {
    return (uint32_t)__cvta_generic_to_shared(p);
}
__device__ __forceinline__ void cp16(uint32_t dst, const void* src) {
    asm volatile("cp.async.cg.shared.global [%0], [%1], 16;"
                 :: "r"(dst), "l"(src) : "memory");
}
__device__ __forceinline__ void cp_commit() {
    asm volatile("cp.async.commit_group;" ::: "memory");
}
__device__ __forceinline__ void cp_wait0() {
    asm volatile("cp.async.wait_group 0;" ::: "memory");
}
__device__ __forceinline__ void ldm_x4(uint32_t* r, uint32_t addr) {
    asm volatile("ldmatrix.sync.aligned.m8n8.x4.shared.b16 {%0,%1,%2,%3}, [%4];"
                 : "=r"(r[0]), "=r"(r[1]), "=r"(r[2]), "=r"(r[3]) : "r"(addr));
}
__device__ __forceinline__ void mma_f16(float* c, const uint32_t* a,
                                        uint32_t b0, uint32_t b1) {
    asm volatile(
        "mma.sync.aligned.m16n8k16.row.col.f32.f16.f16.f32 "
        "{%0,%1,%2,%3},{%4,%5,%6,%7},{%8,%9},{%0,%1,%2,%3};"
        : "+f"(c[0]), "+f"(c[1]), "+f"(c[2]), "+f"(c[3])
        : "r"(a[0]), "r"(a[1]), "r"(a[2]), "r"(a[3]), "r"(b0), "r"(b1));
}
__device__ __forceinline__ void split_store2(__half* hi, __half* lo,
                                             size_t off, float a, float b) {
    __half ha = __float2half_rn(a), hb = __float2half_rn(b);
    __half la = __float2half_rn(a - __half2float(ha));
    __half lb = __float2half_rn(b - __half2float(hb));
    *(__half2*)(hi + off) = __halves2half2(ha, hb);
    *(__half2*)(lo + off) = __halves2half2(la, lb);
}

// ---------------- weight prep: transpose to fp16 ---------------------------
// W [K,N] row-major  ->  T [Npad, K] fp16 (rows >= N zero-filled)
__global__ void wprep_kernel(const float* __restrict__ W, int K, int N, int Npad,
                             __half* __restrict__ T) {
    __shared__ float t[32][33];
    int n0 = blockIdx.x * 32, k0 = blockIdx.y * 32;
    int tx = threadIdx.x, ty = threadIdx.y;
    #pragma unroll
    for (int i = 0; i < 32; i += 8) {
        int n = n0 + tx;
        t[ty + i][tx] = (n < N) ? W[(size_t)(k0 + ty + i) * N + n] : 0.f;
    }
    __syncthreads();
    #pragma unroll
    for (int i = 0; i < 32; i += 8) {
        int n = n0 + ty + i;
        if (n < Npad)
            T[(size_t)n * K + k0 + tx] = __float2half_rn(t[tx][ty + i]);
    }
}

// ---------------- fp16 2-term split GEMM (mma.sync + cp.async) -------------
// C[M,Ntrue] = (Ahi + Alo)[M,K] @ W[N,K]^T ; weights single fp16.
// CTA 128x128, BK=32, 256 thr (8 warps: 4m x 2n, warp tile 32x64).
#define PITCHB 80               /* bytes per smem row: 64 + 16 pad        */
#define ARR_B (128*PITCHB)      /* 10240 bytes per array                  */
#define STAGE_B (3*ARR_B)       /* Ahi, Alo, W                            */
#define GEMM_SMEM (2*STAGE_B)   /* 61440                                   */
__global__ void __launch_bounds__(256, 2)
bgemm_kernel(const __half* __restrict__ Ahi, const __half* __restrict__ Alo,
             const __half* __restrict__ Bw,
             float* __restrict__ C, int Ntrue, int K) {
    extern __shared__ __align__(128) char smem[];
    const uint32_t sbase = smem_u32(smem);
    const int tid = threadIdx.x, lane = tid & 31, warp = tid >> 5;
    const int wm = warp & 3, wn = warp >> 2;
    const int row0 = blockIdx.y * 128, col0 = blockIdx.x * 128;

    const int crow = tid >> 1;                  // 0..127
    const int coff = (tid & 1) * 2;             // chunk pair 0 or 2

    auto load_stage = [&](int k0, int buf) {
        uint32_t sb = sbase + buf * STAGE_B;
        const __half* ga  = Ahi + (size_t)(row0 + crow) * K + k0 + coff * 8;
        const __half* gal = Alo + (size_t)(row0 + crow) * K + k0 + coff * 8;
        const __half* gb  = Bw  + (size_t)(col0 + crow) * K + k0 + coff * 8;
        uint32_t sd = sb + crow * PITCHB + coff * 16;
        cp16(sd,              ga);
        cp16(sd + 16,         ga + 8);
        cp16(sd + ARR_B,      gal);
        cp16(sd + ARR_B+16,   gal + 8);
        cp16(sd + 2*ARR_B,    gb);
        cp16(sd + 2*ARR_B+16, gb + 8);
        cp_commit();
    };

    float acc[2][8][4];
    #pragma unroll
    for (int i = 0; i < 2; i++)
        #pragma unroll
        for (int j = 0; j < 8; j++)
            #pragma unroll
            for (int c = 0; c < 4; c++) acc[i][j][c] = 0.f;

    const int S = K >> 5;
    load_stage(0, 0);

    const int a_r = (lane & 7) + ((lane >> 3) & 1) * 8;
    const int a_c = ((lane >> 4) & 1) * 8;
    const int b_r = (lane & 7) + ((lane >> 4) & 1) * 8;
    const int b_c = ((lane >> 3) & 1) * 8;

    for (int s = 0; s < S; s++) {
        const int buf = s & 1;
        cp_wait0();
        __syncthreads();
        if (s + 1 < S) load_stage((s + 1) << 5, buf ^ 1);

        const uint32_t sb = sbase + buf * STAGE_B;
        #pragma unroll
        for (int k16 = 0; k16 < 32; k16 += 16) {
            uint32_t Ah[2][4], Al[2][4];
            #pragma unroll
            for (int mi = 0; mi < 2; mi++) {
                uint32_t ad = sb + (wm*32 + mi*16 + a_r) * PITCHB + (k16 + a_c) * 2;
                ldm_x4(Ah[mi], ad);
                ldm_x4(Al[mi], ad + ARR_B);
            }
            #pragma unroll
            for (int nj = 0; nj < 4; nj++) {
                uint32_t Bh[4];
                uint32_t bd = sb + 2*ARR_B + (wn*64 + nj*16 + b_r) * PITCHB
                            + (k16 + b_c) * 2;
                ldm_x4(Bh, bd);
                #pragma unroll
                for (int mi = 0; mi < 2; mi++) {
                    #pragma unroll
                    for (int t = 0; t < 2; t++) {
                        float* c = acc[mi][2*nj + t];
                        mma_f16(c, Ah[mi], Bh[2*t], Bh[2*t+1]);
                        mma_f16(c, Al[mi], Bh[2*t], Bh[2*t+1]);
                    }
                }
            }
        }
        __syncthreads();
    }

    const int erow = row0 + wm*32 + (lane >> 2);
    const int ecol0 = col0 + wn*64 + 2*(lane & 3);
    #pragma unroll
    for (int mi = 0; mi < 2; mi++) {
        #pragma unroll
        for (int ni = 0; ni < 8; ni++) {
            int c = ecol0 + ni*8;
            if (c < Ntrue) {
                float* cp0 = C + (size_t)(erow + mi*16) * Ntrue + c;
                *(float2*)cp0 = make_float2(acc[mi][ni][0], acc[mi][ni][1]);
                *(float2*)(cp0 + (size_t)8 * Ntrue) =
                    make_float2(acc[mi][ni][2], acc[mi][ni][3]);
            }
        }
    }
}

// ---------------- mod = silu(time_emb) @ mod_w + mod_b --------------------
__global__ void mod_kernel(const float* __restrict__ te,
                           const float* __restrict__ mod_w,
                           const float* __restrict__ mod_b,
                           float* __restrict__ mod) {
    __shared__ float s[DD];
    int b = blockIdx.y;
    int j = blockIdx.x * 256 + threadIdx.x;
    for (int d = threadIdx.x; d < DD; d += 256) {
        float v = te[b*DD + d];
        s[d] = v / (1.f + __expf(-v));
    }
    __syncthreads();
    float acc = mod_b[j];
    #pragma unroll 4
    for (int d = 0; d < DD; d++)
        acc = fmaf(s[d], mod_w[(size_t)d*SIXD + j], acc);
    mod[b*SIXD + j] = acc;
}

// ---------- rmsnorm*(1+scale)+shift -> fp16 hi/lo  (one CTA per token) ----
__global__ void norm_mod_kernel(const float* __restrict__ x,
                                const float* __restrict__ w,
                                const float* __restrict__ mod,
                                int shift_off, int scale_off,
                                __half* __restrict__ ohi,
                                __half* __restrict__ olo) {
    __shared__ float red[8];
    int t = blockIdx.x;
    int b = t >> 12;
    int tid = threadIdx.x;
    const float4* x4 = (const float4*)(x + (size_t)t*DD);
    float4 v = x4[tid];
    float ss = v.x*v.x + v.y*v.y + v.z*v.z + v.w*v.w;
    #pragma unroll
    for (int o = 16; o > 0; o >>= 1) ss += __shfl_xor_sync(0xffffffffu, ss, o);
    if ((tid & 31) == 0) red[tid >> 5] = ss;
    __syncthreads();
    float tot = red[0]+red[1]+red[2]+red[3]+red[4]+red[5]+red[6]+red[7];
    float inv = rsqrtf(tot * (1.f/DD) + 1e-6f);
    int i = tid * 4;
    const float* mb = mod + b*SIXD;
    float4 wv = *(const float4*)(w + i);
    float4 sc = *(const float4*)(mb + scale_off + i);
    float4 sh = *(const float4*)(mb + shift_off + i);
    float o0 = fmaf(v.x*inv*wv.x, 1.f+sc.x, sh.x);
    float o1 = fmaf(v.y*inv*wv.y, 1.f+sc.y, sh.y);
    float o2 = fmaf(v.z*inv*wv.z, 1.f+sc.z, sh.z);
    float o3 = fmaf(v.w*inv*wv.w, 1.f+sc.w, sh.w);
    size_t off = (size_t)t*DD + i;
    split_store2(ohi, olo, off,     o0, o1);
    split_store2(ohi, olo, off + 2, o2, o3);
}

// ------- fused: x1 = x + gate*hin ; write x1 ; rmsnorm(x1)->fp16 hi/lo -----
__global__ void resid_norm_kernel(const float* __restrict__ x,
                                  const float* __restrict__ hin,
                                  const float* __restrict__ mod, int gate_off,
                                  const float* __restrict__ w,
                                  int shift_off, int scale_off,
                                  float* __restrict__ xout,
                                  __half* __restrict__ ohi,
                                  __half* __restrict__ olo) {
    __shared__ float red[8];
    int t = blockIdx.x;
    int b = t >> 12;
    int tid = threadIdx.x;
    int i = tid * 4;
    const float* mb = mod + b*SIXD;
    float4 xv = ((const float4*)(x + (size_t)t*DD))[tid];
    float4 hv = ((const float4*)(hin + (size_t)t*DD))[tid];
    float4 gv = *(const float4*)(mb + gate_off + i);
    float4 v;
    v.x = fmaf(gv.x, hv.x, xv.x);
    v.y = fmaf(gv.y, hv.y, xv.y);
    v.z = fmaf(gv.z, hv.z, xv.z);
    v.w = fmaf(gv.w, hv.w, xv.w);
    ((float4*)(xout + (size_t)t*DD))[tid] = v;

    float ss = v.x*v.x + v.y*v.y + v.z*v.z + v.w*v.w;
    #pragma unroll
    for (int o = 16; o > 0; o >>= 1) ss += __shfl_xor_sync(0xffffffffu, ss, o);
    if ((tid & 31) == 0) red[tid >> 5] = ss;
    __syncthreads();
    float tot = red[0]+red[1]+red[2]+red[3]+red[4]+red[5]+red[6]+red[7];
    float inv = rsqrtf(tot * (1.f/DD) + 1e-6f);
    float4 wv = *(const float4*)(w + i);
    float4 sc = *(const float4*)(mb + scale_off + i);
    float4 sh = *(const float4*)(mb + shift_off + i);
    float o0 = fmaf(v.x*inv*wv.x, 1.f+sc.x, sh.x);
    float o1 = fmaf(v.y*inv*wv.y, 1.f+sc.y, sh.y);
    float o2 = fmaf(v.z*inv*wv.z, 1.f+sc.z, sh.z);
    float o3 = fmaf(v.w*inv*wv.w, 1.f+sc.w, sh.w);
    size_t off = (size_t)t*DD + i;
    split_store2(ohi, olo, off,     o0, o1);
    split_store2(ohi, olo, off + 2, o2, o3);
}

// ---------------- attention (online softmax), fp16 hi/lo out --------------
__global__ void __launch_bounds__(256, 1)
attn_kernel(const float* __restrict__ qkv,
            __half* __restrict__ ohi, __half* __restrict__ olo) {
    extern __shared__ float sm[];
    float* ks = sm;
    float* vs = sm + SSQ*HDIM;
    int bt = blockIdx.x;
    int h  = blockIdx.y;
    int i  = threadIdx.x;
    size_t base = (size_t)bt * SSQ * (3*DD);
    const float* qp = qkv + base + (size_t)i*(3*DD) + h*HDIM;
    const float* kp = qp + DD;
    const float* vp = qp + 2*DD;

    float4 q[16];
    #pragma unroll
    for (int c = 0; c < 16; c++) q[c] = ((const float4*)qp)[c];
    #pragma unroll
    for (int c = 0; c < 16; c++) ((float4*)(ks + i*HDIM))[c] = ((const float4*)kp)[c];
    #pragma unroll
    for (int c = 0; c < 16; c++) ((float4*)(vs + i*HDIM))[c] = ((const float4*)vp)[c];
    __syncthreads();

    const float scale = 0.125f;
    float m = -1e30f, l = 0.f;
    float acc[64];
    #pragma unroll
    for (int c = 0; c < 64; c++) acc[c] = 0.f;

    for (int j = 0; j < SSQ; j++) {
        const float4* kr = (const float4*)(ks + j*HDIM);
        float s = 0.f;
        #pragma unroll
        for (int c = 0; c < 16; c++) {
            float4 kv = kr[c];
            s = fmaf(q[c].x, kv.x, s); s = fmaf(q[c].y, kv.y, s);
            s = fmaf(q[c].z, kv.z, s); s = fmaf(q[c].w, kv.w, s);
        }
        s *= scale;
        float p;
        if (s > m) {
            float cfac = __expf(m - s);
            l *= cfac;
            #pragma unroll
            for (int c = 0; c < 64; c++) acc[c] *= cfac;
            m = s;
            p = 1.f;
        } else {
            p = __expf(s - m);
        }
        l += p;
        const float4* vr = (const float4*)(vs + j*HDIM);
        #pragma unroll
        for (int c = 0; c < 16; c++) {
            float4 vv = vr[c];
            acc[4*c+0] = fmaf(p, vv.x, acc[4*c+0]);
            acc[4*c+1] = fmaf(p, vv.y, acc[4*c+1]);
            acc[4*c+2] = fmaf(p, vv.z, acc[4*c+2]);
            acc[4*c+3] = fmaf(p, vv.w, acc[4*c+3]);
        }
    }
    float invl = 1.f / l;
    size_t off = (size_t)(bt*SSQ + i)*DD + h*HDIM;
    #pragma unroll
    for (int c = 0; c < 32; c++)
        split_store2(ohi, olo, off + 2*c, acc[2*c]*invl, acc[2*c+1]*invl);
}

// ---------------- out = x + gate[b] * h  ----------------------------------
__global__ void resid_kernel(const float* __restrict__ x,
                             const float* __restrict__ hin,
                             const float* __restrict__ mod, int gate_off,
                             float* __restrict__ out) {
    size_t idx = (size_t)blockIdx.x * 256 + threadIdx.x;
    int d4 = (int)(idx & 255);
    int t  = (int)(idx >> 8);
    int b  = t >> 12;
    float4 g  = ((const float4*)(mod + b*SIXD + gate_off))[d4];
    float4 xv = ((const float4*)x)[idx];
    float4 hv = ((const float4*)hin)[idx];
    float4 o;
    o.x = fmaf(g.x, hv.x, xv.x);
    o.y = fmaf(g.y, hv.y, xv.y);
    o.z = fmaf(g.z, hv.z, xv.z);
    o.w = fmaf(g.w, hv.w, xv.w);
    ((float4*)out)[idx] = o;
}

// ---------------- g = silu(a)*b -> fp16 hi/lo ------------------------------
__global__ void silumul_kernel(const float* __restrict__ a4,
                               const float* __restrict__ b4,
                               __half* __restrict__ ghi,
                               __half* __restrict__ glo, size_t n4) {
    size_t idx = (size_t)blockIdx.x * 256 + threadIdx.x;
    if (idx >= n4) return;
    float4 a = ((const float4*)a4)[idx];
    float4 b = ((const float4*)b4)[idx];
    float o0 = a.x / (1.f + __expf(-a.x)) * b.x;
    float o1 = a.y / (1.f + __expf(-a.y)) * b.y;
    float o2 = a.z / (1.f + __expf(-a.z)) * b.z;
    float o3 = a.w / (1.f + __expf(-a.w)) * b.w;
    split_store2(ghi, glo, idx*4,     o0, o1);
    split_store2(ghi, glo, idx*4 + 2, o2, o3);
}

// ---------------- launch ---------------------------------------------------
extern "C" void kernel_launch(void* const* d_in, const int* in_sizes, int n_in,
                              void* d_out, int out_size) {
    const float* x      = (const float*)d_in[0];
    const float* te     = (const float*)d_in[1];
    const float* n1w    = (const float*)d_in[2];
    const float* n2w    = (const float*)d_in[3];
    const float* qkv_w  = (const float*)d_in[4];
    const float* out_w  = (const float*)d_in[5];
    const float* w1     = (const float*)d_in[6];
    const float* w2     = (const float*)d_in[7];
    const float* w3     = (const float*)d_in[8];
    const float* mod_w  = (const float*)d_in[9];
    const float* mod_b  = (const float*)d_in[10];
    float* out = (float*)d_out;

    float *p_mod, *p_qkv, *p_proj, *p_ff1, *p_ff2, *p_ffo;
    __half *p_hh, *p_hl, *p_ah, *p_al, *p_gh, *p_gl;
    __half *p_wq, *p_wo, *p_w1, *p_w2, *p_w3;
    cudaGetSymbolAddress((void**)&p_mod,  g_mod);
    cudaGetSymbolAddress((void**)&p_hh,   g_hh);
    cudaGetSymbolAddress((void**)&p_hl,   g_hl);
    cudaGetSymbolAddress((void**)&p_qkv,  g_qkv);
    cudaGetSymbolAddress((void**)&p_ah,   g_ah);
    cudaGetSymbolAddress((void**)&p_al,   g_al);
    cudaGetSymbolAddress((void**)&p_proj, g_proj);
    cudaGetSymbolAddress((void**)&p_ff1,  g_ff1);
    cudaGetSymbolAddress((void**)&p_ff2,  g_ff2);
    cudaGetSymbolAddress((void**)&p_gh,   g_gh);
    cudaGetSymbolAddress((void**)&p_gl,   g_gl);
    cudaGetSymbolAddress((void**)&p_ffo,  g_ffo);
    cudaGetSymbolAddress((void**)&p_wq,   g_wq);
    cudaGetSymbolAddress((void**)&p_wo,   g_wo);
    cudaGetSymbolAddress((void**)&p_w1,   g_w1);
    cudaGetSymbolAddress((void**)&p_w2,   g_w2);
    cudaGetSymbolAddress((void**)&p_w3,   g_w3);

    static bool attr_set = false;
    if (!attr_set) {
        cudaFuncSetAttribute(attn_kernel,
                             cudaFuncAttributeMaxDynamicSharedMemorySize,
                             2 * SSQ * HDIM * (int)sizeof(float));
        cudaFuncSetAttribute(bgemm_kernel,
                             cudaFuncAttributeMaxDynamicSharedMemorySize,
                             GEMM_SMEM);
        attr_set = true;
    }

    dim3 tp(32, 8);
    // weight prep: transpose + fp16
    wprep_kernel<<<dim3(3*DD/32, DD/32), tp>>>(qkv_w, DD, 3*DD, 3*DD, p_wq);
    wprep_kernel<<<dim3(DD/32, DD/32), tp>>>(out_w, DD, DD, DD, p_wo);
    wprep_kernel<<<dim3(HPAD/32, DD/32), tp>>>(w1, DD, HIDDEN, HPAD, p_w1);
    wprep_kernel<<<dim3(HPAD/32, DD/32), tp>>>(w2, DD, HIDDEN, HPAD, p_w2);
    wprep_kernel<<<dim3(DD/32, HIDDEN/32), tp>>>(w3, HIDDEN, DD, DD, p_w3);

    // 1. modulation vector
    mod_kernel<<<dim3(SIXD/256, BB), 256>>>(te, mod_w, mod_b, p_mod);
    // 2. h = rmsnorm(x)*(1+scale1)+shift1 -> fp16 hi/lo
    norm_mod_kernel<<<TOKENS, 256>>>(x, n1w, p_mod, 0, 1024, p_hh, p_hl);
    // 3. qkv = h @ qkv_w
    bgemm_kernel<<<dim3(3*DD/128, TOKENS/128), 256, GEMM_SMEM>>>(
        p_hh, p_hl, p_wq, p_qkv, 3*DD, DD);
    // 4. attention -> fp16 hi/lo
    attn_kernel<<<dim3(BB*TT, HH), 256, 2*SSQ*HDIM*sizeof(float)>>>(p_qkv, p_ah, p_al);
    // 5. proj = attn @ out_w
    bgemm_kernel<<<dim3(DD/128, TOKENS/128), 256, GEMM_SMEM>>>(
        p_ah, p_al, p_wo, p_proj, DD, DD);
    // 6+7. x1 = x + gate1*proj -> d_out ; h = rmsnorm(x1)*(1+scale2)+shift2
    resid_norm_kernel<<<TOKENS, 256>>>(x, p_proj, p_mod, 2048,
                                       n2w, 3072, 4096, out, p_hh, p_hl);
    // 8/9. FFN up projections
    bgemm_kernel<<<dim3(HPAD/128, TOKENS/128), 256, GEMM_SMEM>>>(
        p_hh, p_hl, p_w1, p_ff1, HIDDEN, DD);
    bgemm_kernel<<<dim3(HPAD/128, TOKENS/128), 256, GEMM_SMEM>>>(
        p_hh, p_hl, p_w2, p_ff2, HIDDEN, DD);
    // 10. g = silu(ff1)*ff2 -> fp16 hi/lo
    {
        size_t n4 = (size_t)TOKENS * HIDDEN / 4;
        silumul_kernel<<<(unsigned)((n4 + 255) / 256), 256>>>(p_ff1, p_ff2,
                                                              p_gh, p_gl, n4);
    }
    // 11. ffo = g @ w3
    bgemm_kernel<<<dim3(DD/128, TOKENS/128), 256, GEMM_SMEM>>>(
        p_gh, p_gl, p_w3, p_ffo, DD, HIDDEN);
    // 12. out = x1 + gate2*ffo
    resid_kernel<<<TOKENS*DD/4/256, 256>>>(out, p_ffo, p_mod, 5120, out);
}